// round 1
// baseline (speedup 1.0000x reference)
#include <cuda_runtime.h>
#include <math.h>

// Problem constants
#define DIM 1024
#define NH  16
#define HD  64
#define B_  2
#define T_  2048
#define M_TOT (B_ * T_)          // 4096 rows for all projections

// Scratch (device globals; no allocation allowed)
__device__ float g_q[B_ * NH * T_ * HD];     // [B,H,T,Hd] 16 MB
__device__ float g_ctx[B_ * T_ * DIM];       // [B,T,H*Hd] 16 MB

// ---------------------------------------------------------------------------
// GEMM: C = A[M,K] @ W[N,K]^T + bias[N]
// mode 0: C row-major [M,N]
// mode 1: scatter to [B,H,T,Hd]  (m = b*T+t, n = h*HD+hd)
// Block tile 128x64, K-tile 16, 256 threads, 8x4 per thread.
// ---------------------------------------------------------------------------
#define BM 128
#define BN 64
#define BKK 16

__global__ __launch_bounds__(256) void gemm_bias_kernel(
    const float* __restrict__ A, const float* __restrict__ W,
    const float* __restrict__ bias, float* __restrict__ C,
    int K, int N, int mode)
{
    __shared__ float As[BKK][BM + 4];   // stride 132 (x4B=528, 16B aligned per row)
    __shared__ float Bs[BKK][BN + 4];   // stride 68

    const int tid = threadIdx.x;
    const int ty  = tid >> 4;           // 0..15 -> m-group (8 rows each)
    const int tx  = tid & 15;           // 0..15 -> n-group (4 cols each)
    const int m0  = blockIdx.y * BM;
    const int n0  = blockIdx.x * BN;

    float acc[8][4];
    #pragma unroll
    for (int i = 0; i < 8; i++)
        #pragma unroll
        for (int j = 0; j < 4; j++) acc[i][j] = 0.0f;

    for (int k0 = 0; k0 < K; k0 += BKK) {
        // Load A tile: 128x16 = 512 float4, 2 per thread, transposed into As[k][m]
        #pragma unroll
        for (int l = 0; l < 2; l++) {
            int f   = tid + l * 256;    // float4 index 0..511
            int row = f >> 2;           // 4 float4 per row of 16 floats
            int c4  = f & 3;
            float4 v = *reinterpret_cast<const float4*>(&A[(size_t)(m0 + row) * K + k0 + c4 * 4]);
            As[c4 * 4 + 0][row] = v.x;
            As[c4 * 4 + 1][row] = v.y;
            As[c4 * 4 + 2][row] = v.z;
            As[c4 * 4 + 3][row] = v.w;
        }
        // Load W tile: 64x16 = 256 float4, 1 per thread, transposed into Bs[k][n]
        {
            int f   = tid;
            int row = f >> 2;
            int c4  = f & 3;
            float4 v = *reinterpret_cast<const float4*>(&W[(size_t)(n0 + row) * K + k0 + c4 * 4]);
            Bs[c4 * 4 + 0][row] = v.x;
            Bs[c4 * 4 + 1][row] = v.y;
            Bs[c4 * 4 + 2][row] = v.z;
            Bs[c4 * 4 + 3][row] = v.w;
        }
        __syncthreads();

        #pragma unroll
        for (int kk = 0; kk < BKK; kk++) {
            float4 a0 = *reinterpret_cast<float4*>(&As[kk][ty * 8]);
            float4 a1 = *reinterpret_cast<float4*>(&As[kk][ty * 8 + 4]);
            float4 b0 = *reinterpret_cast<float4*>(&Bs[kk][tx * 4]);
            float a[8] = {a0.x, a0.y, a0.z, a0.w, a1.x, a1.y, a1.z, a1.w};
            float b[4] = {b0.x, b0.y, b0.z, b0.w};
            #pragma unroll
            for (int i = 0; i < 8; i++)
                #pragma unroll
                for (int j = 0; j < 4; j++)
                    acc[i][j] = fmaf(a[i], b[j], acc[i][j]);
        }
        __syncthreads();
    }

    // Epilogue
    #pragma unroll
    for (int i = 0; i < 8; i++) {
        int m = m0 + ty * 8 + i;
        #pragma unroll
        for (int j = 0; j < 4; j++) {
            int n = n0 + tx * 4 + j;
            float val = acc[i][j] + bias[n];
            if (mode == 0) {
                C[(size_t)m * N + n] = val;
            } else {
                int b  = m >> 11;       // / T_
                int t  = m & (T_ - 1);
                int h  = n >> 6;        // / HD
                int hd = n & (HD - 1);
                C[((((size_t)b * NH + h) * T_) + t) * HD + hd] = val;
            }
        }
    }
}

// ---------------------------------------------------------------------------
// Flash attention (causal), fp32.
// q,k,v: [B,H,T,HD]; ctx out: [B,T,H,HD]
// Block: 128 threads = 128 query rows. Key tiles of 32 rows in smem.
// ---------------------------------------------------------------------------
#define AQ 128
#define AK 32

__global__ __launch_bounds__(128) void attn_kernel(
    const float* __restrict__ q, const float* __restrict__ k,
    const float* __restrict__ v, float* __restrict__ ctx)
{
    const int t  = threadIdx.x;        // 0..127
    const int qt = blockIdx.x;         // 0..15
    const int h  = blockIdx.y;         // 0..15
    const int b  = blockIdx.z;         // 0..1

    const size_t head_off = ((size_t)b * NH + h) * T_ * HD;
    const float* qb = q + head_off;
    const float* kb = k + head_off;
    const float* vb = v + head_off;

    const int qi = qt * AQ + t;        // this thread's query row

    // Load q row into registers, pre-scaled by 1/sqrt(HD)
    float qr[HD];
    #pragma unroll
    for (int c = 0; c < HD; c += 4) {
        float4 vq = *reinterpret_cast<const float4*>(&qb[(size_t)qi * HD + c]);
        qr[c + 0] = vq.x * 0.125f;
        qr[c + 1] = vq.y * 0.125f;
        qr[c + 2] = vq.z * 0.125f;
        qr[c + 3] = vq.w * 0.125f;
    }

    float accv[HD];
    #pragma unroll
    for (int c = 0; c < HD; c++) accv[c] = 0.0f;
    float mi = -INFINITY;
    float li = 0.0f;

    __shared__ float Ks[AK][HD];
    __shared__ float Vs[AK][HD];

    const int kend = qt * AQ + AQ;     // causal bound (exclusive), full tiles

    for (int j0 = 0; j0 < kend; j0 += AK) {
        // Cooperative load K,V tiles: 32x64 = 2048 floats = 512 float4 each;
        // 4 float4 per thread per tile.
        #pragma unroll
        for (int l = 0; l < 4; l++) {
            int f   = t + l * 128;      // 0..511
            int row = f >> 4;           // 16 float4 per row
            int c   = f & 15;
            *reinterpret_cast<float4*>(&Ks[row][c * 4]) =
                *reinterpret_cast<const float4*>(&kb[(size_t)(j0 + row) * HD + c * 4]);
            *reinterpret_cast<float4*>(&Vs[row][c * 4]) =
                *reinterpret_cast<const float4*>(&vb[(size_t)(j0 + row) * HD + c * 4]);
        }
        __syncthreads();

        // Scores for this tile
        float s[AK];
        #pragma unroll 4
        for (int j = 0; j < AK; j++) {
            float d = 0.0f;
            #pragma unroll
            for (int c = 0; c < HD; c += 4) {
                float4 kv = *reinterpret_cast<float4*>(&Ks[j][c]);
                d = fmaf(qr[c + 0], kv.x, d);
                d = fmaf(qr[c + 1], kv.y, d);
                d = fmaf(qr[c + 2], kv.z, d);
                d = fmaf(qr[c + 3], kv.w, d);
            }
            s[j] = d;
        }
        // Causal mask (only tiles overlapping/after the diagonal need it)
        if (j0 + AK - 1 > qi) {
            #pragma unroll
            for (int j = 0; j < AK; j++)
                if (j0 + j > qi) s[j] = -INFINITY;
        }

        // Online softmax update
        float mt = -INFINITY;
        #pragma unroll
        for (int j = 0; j < AK; j++) mt = fmaxf(mt, s[j]);
        float mnew  = fmaxf(mi, mt);
        float scale = __expf(mi - mnew);   // first tile: mi=-inf, mnew finite -> 0
        li *= scale;
        #pragma unroll
        for (int c = 0; c < HD; c++) accv[c] *= scale;

        #pragma unroll 4
        for (int j = 0; j < AK; j++) {
            float p = __expf(s[j] - mnew);
            li += p;
            #pragma unroll
            for (int c = 0; c < HD; c += 4) {
                float4 vv = *reinterpret_cast<float4*>(&Vs[j][c]);
                accv[c + 0] = fmaf(p, vv.x, accv[c + 0]);
                accv[c + 1] = fmaf(p, vv.y, accv[c + 1]);
                accv[c + 2] = fmaf(p, vv.z, accv[c + 2]);
                accv[c + 3] = fmaf(p, vv.w, accv[c + 3]);
            }
        }
        mi = mnew;
        __syncthreads();
    }

    const float inv = 1.0f / li;
    // ctx layout [B,T,H,HD] so the output GEMM reads contiguous [M, DIM] rows
    float* outp = ctx + (((size_t)b * T_ + qi) * NH + h) * HD;
    #pragma unroll
    for (int c = 0; c < HD; c += 4) {
        float4 o;
        o.x = accv[c + 0] * inv;
        o.y = accv[c + 1] * inv;
        o.z = accv[c + 2] * inv;
        o.w = accv[c + 3] * inv;
        *reinterpret_cast<float4*>(&outp[c]) = o;
    }
}

// ---------------------------------------------------------------------------
// kernel_launch
// Inputs: x, Wq, bq, Wk, bk, Wv, bv, Wo, bo (all float32)
// Output: [out | k | v], each B*T*DIM = 4,194,304 floats
// ---------------------------------------------------------------------------
extern "C" void kernel_launch(void* const* d_in, const int* in_sizes, int n_in,
                              void* d_out, int out_size)
{
    const float* x  = (const float*)d_in[0];
    const float* Wq = (const float*)d_in[1];
    const float* bq = (const float*)d_in[2];
    const float* Wk = (const float*)d_in[3];
    const float* bk = (const float*)d_in[4];
    const float* Wv = (const float*)d_in[5];
    const float* bv = (const float*)d_in[6];
    const float* Wo = (const float*)d_in[7];
    const float* bo = (const float*)d_in[8];

    float* out   = (float*)d_out;
    float* k_out = out + (size_t)B_ * T_ * DIM;       // [B,H,T,Hd]
    float* v_out = out + (size_t)2 * B_ * T_ * DIM;   // [B,H,T,Hd]

    float* qbuf   = nullptr;
    float* ctxbuf = nullptr;
    cudaGetSymbolAddress((void**)&qbuf,   g_q);
    cudaGetSymbolAddress((void**)&ctxbuf, g_ctx);

    dim3 ggrid(DIM / BN, M_TOT / BM);   // (16, 32)

    // QKV projections (mode 1: scatter to [B,H,T,Hd])
    gemm_bias_kernel<<<ggrid, 256>>>(x, Wq, bq, qbuf,  DIM, DIM, 1);
    gemm_bias_kernel<<<ggrid, 256>>>(x, Wk, bk, k_out, DIM, DIM, 1);
    gemm_bias_kernel<<<ggrid, 256>>>(x, Wv, bv, v_out, DIM, DIM, 1);

    // Causal flash attention -> ctx [B,T,H,Hd]
    dim3 agrid(T_ / AQ, NH, B_);        // (16, 16, 2)
    attn_kernel<<<agrid, 128>>>(qbuf, k_out, v_out, ctxbuf);

    // Output projection (mode 0: row-major [M,N] = [B*T, DIM])
    gemm_bias_kernel<<<ggrid, 256>>>(ctxbuf, Wo, bo, out, DIM, DIM, 0);
}

// round 3
// speedup vs baseline: 1.3633x; 1.3633x over previous
#include <cuda_runtime.h>
#include <cuda_bf16.h>
#include <cstdint>
#include <math.h>

// Problem constants
#define DIM 1024
#define NH  16
#define HD  64
#define B_  2
#define T_  2048
#define M_TOT (B_ * T_)          // 4096 rows for all projections

// Scratch (device globals; no allocation allowed)
__device__ float g_q[B_ * NH * T_ * HD];     // [B,H,T,Hd] 16 MB
__device__ float g_ctx[B_ * T_ * DIM];       // [B,T,H*Hd] 16 MB

// ===========================================================================
// Helpers: mma.sync bf16 + ldmatrix (plain sm_103-compatible, no 'a' features)
// ===========================================================================
__device__ __forceinline__ uint32_t smem_to_u32(const void* p) {
    uint32_t a;
    asm("{ .reg .u64 t; cvta.to.shared.u64 t, %1; cvt.u32.u64 %0, t; }"
        : "=r"(a) : "l"(p));
    return a;
}

#define LDSM_X4(r, addr) \
    asm volatile("ldmatrix.sync.aligned.m8n8.x4.shared.b16 {%0,%1,%2,%3}, [%4];" \
        : "=r"((r)[0]), "=r"((r)[1]), "=r"((r)[2]), "=r"((r)[3]) : "r"(addr))

#define MMA_BF16(d, a, b) \
    asm volatile("mma.sync.aligned.m16n8k16.row.col.f32.bf16.bf16.f32 " \
        "{%0,%1,%2,%3}, {%4,%5,%6,%7}, {%8,%9}, {%0,%1,%2,%3};" \
        : "+f"((d)[0]), "+f"((d)[1]), "+f"((d)[2]), "+f"((d)[3]) \
        : "r"((a)[0]), "r"((a)[1]), "r"((a)[2]), "r"((a)[3]), \
          "r"((b)[0]), "r"((b)[1]))

// Split a float4 into bf16 hi + bf16 residual-lo (memory order preserved)
__device__ __forceinline__ void split4(float4 v, uint2& hi, uint2& lo) {
    __nv_bfloat162 h01 = __floats2bfloat162_rn(v.x, v.y);
    __nv_bfloat162 h23 = __floats2bfloat162_rn(v.z, v.w);
    __nv_bfloat162 l01 = __floats2bfloat162_rn(v.x - __bfloat162float(h01.x),
                                               v.y - __bfloat162float(h01.y));
    __nv_bfloat162 l23 = __floats2bfloat162_rn(v.z - __bfloat162float(h23.x),
                                               v.w - __bfloat162float(h23.y));
    hi = make_uint2(*reinterpret_cast<uint32_t*>(&h01),
                    *reinterpret_cast<uint32_t*>(&h23));
    lo = make_uint2(*reinterpret_cast<uint32_t*>(&l01),
                    *reinterpret_cast<uint32_t*>(&l23));
}

// ===========================================================================
// Split-bf16 GEMM via mma.sync: C = A[M,1024] @ W[1024,1024]^T + bias
// 3-term: Ah*Bh + Al*Bh + Ah*Bl  (error ~2^-17 per element)
// Block tile 128x128, K-chunk 64, 256 threads (8 warps, 2x4), warp tile 64x32.
// SMEM tiles padded to 72 halves/row (144B) -> conflict-free ldmatrix/STS.
// Double-buffered, LDG-prefetch one chunk ahead into registers.
// mode 0: C row-major [M,1024]; mode 1: scatter to [B,H,T,Hd].
// ===========================================================================
#define BK 64
#define ROW_B 144                       // bytes per padded row (72 halves)
#define TILE_BYTES (128 * ROW_B)        // 18432
#define STAGE_BYTES (4 * TILE_BYTES)    // Ah, Al, Bh, Bl = 73728
#define GEMM_SMEM (2 * STAGE_BYTES)     // 147456
#define N_CHUNKS 16                     // K=1024 / 64

__global__ void __launch_bounds__(256, 1) gemm_tc_kernel(
    const float* __restrict__ A, const float* __restrict__ W,
    const float* __restrict__ bias, float* __restrict__ C, int mode)
{
    extern __shared__ char smem[];
    const uint32_t sb = smem_to_u32(smem);
    const int tid    = threadIdx.x;
    const int lane   = tid & 31;
    const int wid    = tid >> 5;
    const int warp_m = wid & 1;          // 0..1  (64 rows each)
    const int warp_n = wid >> 1;         // 0..3  (32 cols each)
    const int m0 = blockIdx.y * 128;
    const int n0 = blockIdx.x * 128;

    float acc[4][4][4];
    #pragma unroll
    for (int mi = 0; mi < 4; mi++)
        #pragma unroll
        for (int ni = 0; ni < 4; ni++)
            #pragma unroll
            for (int j = 0; j < 4; j++) acc[mi][ni][j] = 0.0f;

    // ldmatrix lane offsets
    const int r    = lane & 7;
    const int quad = lane >> 3;
    const uint32_t a_lane_off =
        (uint32_t)(warp_m * 64 + (quad & 1) * 8 + r) * ROW_B + (quad >> 1) * 16;
    const uint32_t b_lane_off =
        (uint32_t)(warp_n * 32 + (quad >> 1) * 8 + r) * ROW_B + (quad & 1) * 16;

    float4 rA[8], rW[8];

    // ---- load chunk `c` from gmem into registers ----
    auto LOAD = [&](int c) {
        const int k0 = c * BK;
        #pragma unroll
        for (int l = 0; l < 8; l++) {
            const int f   = l * 256 + tid;
            const int row = f >> 4;          // 16 float4 per 64-float row
            const int c4  = f & 15;
            rA[l] = *reinterpret_cast<const float4*>(
                &A[(size_t)(m0 + row) * DIM + k0 + c4 * 4]);
            rW[l] = *reinterpret_cast<const float4*>(
                &W[(size_t)(n0 + row) * DIM + k0 + c4 * 4]);
        }
    };

    // ---- split + store registers into smem stage p ----
    auto STORE = [&](int p) {
        char* base = smem + p * STAGE_BYTES;
        #pragma unroll
        for (int l = 0; l < 8; l++) {
            const int f   = l * 256 + tid;
            const int row = f >> 4;
            const int c4  = f & 15;
            const uint32_t off = (uint32_t)row * ROW_B + c4 * 8;
            uint2 hi, lo;
            split4(rA[l], hi, lo);
            *reinterpret_cast<uint2*>(base + off)              = hi;   // Ah
            *reinterpret_cast<uint2*>(base + TILE_BYTES + off) = lo;   // Al
            split4(rW[l], hi, lo);
            *reinterpret_cast<uint2*>(base + 2 * TILE_BYTES + off) = hi; // Bh
            *reinterpret_cast<uint2*>(base + 3 * TILE_BYTES + off) = lo; // Bl
        }
    };

    LOAD(0);
    STORE(0);
    __syncthreads();

    for (int c = 0; c < N_CHUNKS; ++c) {
        const int p = c & 1;
        if (c + 1 < N_CHUNKS) LOAD(c + 1);   // prefetch (overlaps with MMA)

        const uint32_t stage = sb + p * STAGE_BYTES;
        #pragma unroll
        for (int ks = 0; ks < 4; ++ks) {
            uint32_t ah[4][4], al[4][4];
            #pragma unroll
            for (int mi = 0; mi < 4; mi++) {
                const uint32_t addr =
                    stage + a_lane_off + mi * (16 * ROW_B) + ks * 32;
                LDSM_X4(ah[mi], addr);
                LDSM_X4(al[mi], addr + TILE_BYTES);
            }
            uint32_t bh[4][2], bl[4][2];
            #pragma unroll
            for (int pr = 0; pr < 2; pr++) {
                const uint32_t addr =
                    stage + 2 * TILE_BYTES + b_lane_off + pr * (16 * ROW_B) + ks * 32;
                LDSM_X4(&bh[2 * pr][0], addr);
                LDSM_X4(&bl[2 * pr][0], addr + TILE_BYTES);
            }
            #pragma unroll
            for (int mi = 0; mi < 4; mi++)
                #pragma unroll
                for (int ni = 0; ni < 4; ni++) {
                    MMA_BF16(acc[mi][ni], ah[mi], bh[ni]);
                    MMA_BF16(acc[mi][ni], al[mi], bh[ni]);
                    MMA_BF16(acc[mi][ni], ah[mi], bl[ni]);
                }
        }

        if (c + 1 < N_CHUNKS) STORE(1 - p);
        __syncthreads();
    }

    // ---- epilogue ----
    const int gid  = lane >> 2;
    const int tid4 = lane & 3;
    #pragma unroll
    for (int mi = 0; mi < 4; mi++) {
        #pragma unroll
        for (int ni = 0; ni < 4; ni++) {
            const int n = n0 + warp_n * 32 + ni * 8 + tid4 * 2;
            const float2 bb = *reinterpret_cast<const float2*>(&bias[n]);
            #pragma unroll
            for (int hrow = 0; hrow < 2; hrow++) {
                const int m = m0 + warp_m * 64 + mi * 16 + gid + hrow * 8;
                float2 o;
                o.x = acc[mi][ni][hrow * 2 + 0] + bb.x;
                o.y = acc[mi][ni][hrow * 2 + 1] + bb.y;
                if (mode == 0) {
                    *reinterpret_cast<float2*>(&C[(size_t)m * DIM + n]) = o;
                } else {
                    const int b  = m >> 11;
                    const int t  = m & (T_ - 1);
                    const int h  = n >> 6;
                    const int hd = n & (HD - 1);
                    *reinterpret_cast<float2*>(
                        &C[((((size_t)b * NH + h) * T_) + t) * HD + hd]) = o;
                }
            }
        }
    }
}

// ---------------------------------------------------------------------------
// Flash attention (causal), fp32 SIMT (R3 target).
// q,k,v: [B,H,T,HD]; ctx out: [B,T,H,HD]
// ---------------------------------------------------------------------------
#define AQ 128
#define AK 32

__global__ __launch_bounds__(128) void attn_kernel(
    const float* __restrict__ q, const float* __restrict__ k,
    const float* __restrict__ v, float* __restrict__ ctx)
{
    const int t  = threadIdx.x;
    const int qt = blockIdx.x;
    const int h  = blockIdx.y;
    const int b  = blockIdx.z;

    const size_t head_off = ((size_t)b * NH + h) * T_ * HD;
    const float* qb = q + head_off;
    const float* kb = k + head_off;
    const float* vb = v + head_off;

    const int qi = qt * AQ + t;

    float qr[HD];
    #pragma unroll
    for (int c = 0; c < HD; c += 4) {
        float4 vq = *reinterpret_cast<const float4*>(&qb[(size_t)qi * HD + c]);
        qr[c + 0] = vq.x * 0.125f;
        qr[c + 1] = vq.y * 0.125f;
        qr[c + 2] = vq.z * 0.125f;
        qr[c + 3] = vq.w * 0.125f;
    }

    float accv[HD];
    #pragma unroll
    for (int c = 0; c < HD; c++) accv[c] = 0.0f;
    float mi = -INFINITY;
    float li = 0.0f;

    __shared__ float Ks[AK][HD];
    __shared__ float Vs[AK][HD];

    const int kend = qt * AQ + AQ;

    for (int j0 = 0; j0 < kend; j0 += AK) {
        #pragma unroll
        for (int l = 0; l < 4; l++) {
            int f   = t + l * 128;
            int row = f >> 4;
            int c   = f & 15;
            *reinterpret_cast<float4*>(&Ks[row][c * 4]) =
                *reinterpret_cast<const float4*>(&kb[(size_t)(j0 + row) * HD + c * 4]);
            *reinterpret_cast<float4*>(&Vs[row][c * 4]) =
                *reinterpret_cast<const float4*>(&vb[(size_t)(j0 + row) * HD + c * 4]);
        }
        __syncthreads();

        float s[AK];
        #pragma unroll 4
        for (int j = 0; j < AK; j++) {
            float d = 0.0f;
            #pragma unroll
            for (int c = 0; c < HD; c += 4) {
                float4 kv = *reinterpret_cast<float4*>(&Ks[j][c]);
                d = fmaf(qr[c + 0], kv.x, d);
                d = fmaf(qr[c + 1], kv.y, d);
                d = fmaf(qr[c + 2], kv.z, d);
                d = fmaf(qr[c + 3], kv.w, d);
            }
            s[j] = d;
        }
        if (j0 + AK - 1 > qi) {
            #pragma unroll
            for (int j = 0; j < AK; j++)
                if (j0 + j > qi) s[j] = -INFINITY;
        }

        float mt = -INFINITY;
        #pragma unroll
        for (int j = 0; j < AK; j++) mt = fmaxf(mt, s[j]);
        float mnew  = fmaxf(mi, mt);
        float scale = __expf(mi - mnew);
        li *= scale;
        #pragma unroll
        for (int c = 0; c < HD; c++) accv[c] *= scale;

        #pragma unroll 4
        for (int j = 0; j < AK; j++) {
            float p = __expf(s[j] - mnew);
            li += p;
            #pragma unroll
            for (int c = 0; c < HD; c += 4) {
                float4 vv = *reinterpret_cast<float4*>(&Vs[j][c]);
                accv[c + 0] = fmaf(p, vv.x, accv[c + 0]);
                accv[c + 1] = fmaf(p, vv.y, accv[c + 1]);
                accv[c + 2] = fmaf(p, vv.z, accv[c + 2]);
                accv[c + 3] = fmaf(p, vv.w, accv[c + 3]);
            }
        }
        mi = mnew;
        __syncthreads();
    }

    const float inv = 1.0f / li;
    float* outp = ctx + (((size_t)b * T_ + qi) * NH + h) * HD;
    #pragma unroll
    for (int c = 0; c < HD; c += 4) {
        float4 o;
        o.x = accv[c + 0] * inv;
        o.y = accv[c + 1] * inv;
        o.z = accv[c + 2] * inv;
        o.w = accv[c + 3] * inv;
        *reinterpret_cast<float4*>(&outp[c]) = o;
    }
}

// ---------------------------------------------------------------------------
// kernel_launch
// ---------------------------------------------------------------------------
extern "C" void kernel_launch(void* const* d_in, const int* in_sizes, int n_in,
                              void* d_out, int out_size)
{
    const float* x  = (const float*)d_in[0];
    const float* Wq = (const float*)d_in[1];
    const float* bq = (const float*)d_in[2];
    const float* Wk = (const float*)d_in[3];
    const float* bk = (const float*)d_in[4];
    const float* Wv = (const float*)d_in[5];
    const float* bv = (const float*)d_in[6];
    const float* Wo = (const float*)d_in[7];
    const float* bo = (const float*)d_in[8];

    float* out   = (float*)d_out;
    float* k_out = out + (size_t)B_ * T_ * DIM;       // [B,H,T,Hd]
    float* v_out = out + (size_t)2 * B_ * T_ * DIM;   // [B,H,T,Hd]

    float* qbuf   = nullptr;
    float* ctxbuf = nullptr;
    cudaGetSymbolAddress((void**)&qbuf,   g_q);
    cudaGetSymbolAddress((void**)&ctxbuf, g_ctx);

    cudaFuncSetAttribute(gemm_tc_kernel,
                         cudaFuncAttributeMaxDynamicSharedMemorySize, GEMM_SMEM);

    dim3 ggrid(DIM / 128, M_TOT / 128);   // (8, 32)

    // QKV projections (mode 1: scatter to [B,H,T,Hd])
    gemm_tc_kernel<<<ggrid, 256, GEMM_SMEM>>>(x, Wq, bq, qbuf,  1);
    gemm_tc_kernel<<<ggrid, 256, GEMM_SMEM>>>(x, Wk, bk, k_out, 1);
    gemm_tc_kernel<<<ggrid, 256, GEMM_SMEM>>>(x, Wv, bv, v_out, 1);

    // Causal flash attention -> ctx [B,T,H,Hd]
    dim3 agrid(T_ / AQ, NH, B_);          // (16, 16, 2)
    attn_kernel<<<agrid, 128>>>(qbuf, k_out, v_out, ctxbuf);

    // Output projection (mode 0: row-major [B*T, DIM])
    gemm_tc_kernel<<<ggrid, 256, GEMM_SMEM>>>(ctxbuf, Wo, bo, out, 0);
}

// round 4
// speedup vs baseline: 4.4500x; 3.2642x over previous
#include <cuda_runtime.h>
#include <cuda_bf16.h>
#include <cstdint>
#include <math.h>

// Problem constants
#define DIM 1024
#define NH  16
#define HD  64
#define B_  2
#define T_  2048
#define M_TOT (B_ * T_)          // 4096 rows for all projections

// Scratch (device globals; no allocation allowed)
__device__ float g_q[B_ * NH * T_ * HD];     // [B,H,T,Hd] 16 MB
__device__ float g_ctx[B_ * T_ * DIM];       // [B,T,H*Hd] 16 MB

// ===========================================================================
// Helpers: mma.sync bf16 + ldmatrix (plain sm_103-compatible)
// ===========================================================================
__device__ __forceinline__ uint32_t smem_to_u32(const void* p) {
    uint32_t a;
    asm("{ .reg .u64 t; cvta.to.shared.u64 t, %1; cvt.u32.u64 %0, t; }"
        : "=r"(a) : "l"(p));
    return a;
}

#define LDSM_X4(r, addr) \
    asm volatile("ldmatrix.sync.aligned.m8n8.x4.shared.b16 {%0,%1,%2,%3}, [%4];" \
        : "=r"((r)[0]), "=r"((r)[1]), "=r"((r)[2]), "=r"((r)[3]) : "r"(addr))

#define LDSM_X4_T(r, addr) \
    asm volatile("ldmatrix.sync.aligned.m8n8.x4.trans.shared.b16 {%0,%1,%2,%3}, [%4];" \
        : "=r"((r)[0]), "=r"((r)[1]), "=r"((r)[2]), "=r"((r)[3]) : "r"(addr))

#define MMA_BF16(d, a, b) \
    asm volatile("mma.sync.aligned.m16n8k16.row.col.f32.bf16.bf16.f32 " \
        "{%0,%1,%2,%3}, {%4,%5,%6,%7}, {%8,%9}, {%0,%1,%2,%3};" \
        : "+f"((d)[0]), "+f"((d)[1]), "+f"((d)[2]), "+f"((d)[3]) \
        : "r"((a)[0]), "r"((a)[1]), "r"((a)[2]), "r"((a)[3]), \
          "r"((b)[0]), "r"((b)[1]))

// Split a float4 into bf16 hi + bf16 residual-lo (memory order preserved)
__device__ __forceinline__ void split4(float4 v, uint2& hi, uint2& lo) {
    __nv_bfloat162 h01 = __floats2bfloat162_rn(v.x, v.y);
    __nv_bfloat162 h23 = __floats2bfloat162_rn(v.z, v.w);
    __nv_bfloat162 l01 = __floats2bfloat162_rn(v.x - __bfloat162float(h01.x),
                                               v.y - __bfloat162float(h01.y));
    __nv_bfloat162 l23 = __floats2bfloat162_rn(v.z - __bfloat162float(h23.x),
                                               v.w - __bfloat162float(h23.y));
    hi = make_uint2(*reinterpret_cast<uint32_t*>(&h01),
                    *reinterpret_cast<uint32_t*>(&h23));
    lo = make_uint2(*reinterpret_cast<uint32_t*>(&l01),
                    *reinterpret_cast<uint32_t*>(&l23));
}

// ===========================================================================
// Split-bf16 GEMM via mma.sync (unchanged from R3 — passed at ~91us/GEMM)
// ===========================================================================
#define BK 64
#define ROW_B 144
#define TILE_BYTES (128 * ROW_B)
#define STAGE_BYTES (4 * TILE_BYTES)
#define GEMM_SMEM (2 * STAGE_BYTES)
#define N_CHUNKS 16

__global__ void __launch_bounds__(256, 1) gemm_tc_kernel(
    const float* __restrict__ A, const float* __restrict__ W,
    const float* __restrict__ bias, float* __restrict__ C, int mode)
{
    extern __shared__ char smem[];
    const uint32_t sb = smem_to_u32(smem);
    const int tid    = threadIdx.x;
    const int lane   = tid & 31;
    const int wid    = tid >> 5;
    const int warp_m = wid & 1;
    const int warp_n = wid >> 1;
    const int m0 = blockIdx.y * 128;
    const int n0 = blockIdx.x * 128;

    float acc[4][4][4];
    #pragma unroll
    for (int mi = 0; mi < 4; mi++)
        #pragma unroll
        for (int ni = 0; ni < 4; ni++)
            #pragma unroll
            for (int j = 0; j < 4; j++) acc[mi][ni][j] = 0.0f;

    const int r    = lane & 7;
    const int quad = lane >> 3;
    const uint32_t a_lane_off =
        (uint32_t)(warp_m * 64 + (quad & 1) * 8 + r) * ROW_B + (quad >> 1) * 16;
    const uint32_t b_lane_off =
        (uint32_t)(warp_n * 32 + (quad >> 1) * 8 + r) * ROW_B + (quad & 1) * 16;

    float4 rA[8], rW[8];

    auto LOAD = [&](int c) {
        const int k0 = c * BK;
        #pragma unroll
        for (int l = 0; l < 8; l++) {
            const int f   = l * 256 + tid;
            const int row = f >> 4;
            const int c4  = f & 15;
            rA[l] = *reinterpret_cast<const float4*>(
                &A[(size_t)(m0 + row) * DIM + k0 + c4 * 4]);
            rW[l] = *reinterpret_cast<const float4*>(
                &W[(size_t)(n0 + row) * DIM + k0 + c4 * 4]);
        }
    };

    auto STORE = [&](int p) {
        char* base = smem + p * STAGE_BYTES;
        #pragma unroll
        for (int l = 0; l < 8; l++) {
            const int f   = l * 256 + tid;
            const int row = f >> 4;
            const int c4  = f & 15;
            const uint32_t off = (uint32_t)row * ROW_B + c4 * 8;
            uint2 hi, lo;
            split4(rA[l], hi, lo);
            *reinterpret_cast<uint2*>(base + off)              = hi;
            *reinterpret_cast<uint2*>(base + TILE_BYTES + off) = lo;
            split4(rW[l], hi, lo);
            *reinterpret_cast<uint2*>(base + 2 * TILE_BYTES + off) = hi;
            *reinterpret_cast<uint2*>(base + 3 * TILE_BYTES + off) = lo;
        }
    };

    LOAD(0);
    STORE(0);
    __syncthreads();

    for (int c = 0; c < N_CHUNKS; ++c) {
        const int p = c & 1;
        if (c + 1 < N_CHUNKS) LOAD(c + 1);

        const uint32_t stage = sb + p * STAGE_BYTES;
        #pragma unroll
        for (int ks = 0; ks < 4; ++ks) {
            uint32_t ah[4][4], al[4][4];
            #pragma unroll
            for (int mi = 0; mi < 4; mi++) {
                const uint32_t addr =
                    stage + a_lane_off + mi * (16 * ROW_B) + ks * 32;
                LDSM_X4(ah[mi], addr);
                LDSM_X4(al[mi], addr + TILE_BYTES);
            }
            uint32_t bh[4][2], bl[4][2];
            #pragma unroll
            for (int pr = 0; pr < 2; pr++) {
                const uint32_t addr =
                    stage + 2 * TILE_BYTES + b_lane_off + pr * (16 * ROW_B) + ks * 32;
                LDSM_X4(&bh[2 * pr][0], addr);
                LDSM_X4(&bl[2 * pr][0], addr + TILE_BYTES);
            }
            #pragma unroll
            for (int mi = 0; mi < 4; mi++)
                #pragma unroll
                for (int ni = 0; ni < 4; ni++) {
                    MMA_BF16(acc[mi][ni], ah[mi], bh[ni]);
                    MMA_BF16(acc[mi][ni], al[mi], bh[ni]);
                    MMA_BF16(acc[mi][ni], ah[mi], bl[ni]);
                }
        }

        if (c + 1 < N_CHUNKS) STORE(1 - p);
        __syncthreads();
    }

    const int gid  = lane >> 2;
    const int tid4 = lane & 3;
    #pragma unroll
    for (int mi = 0; mi < 4; mi++) {
        #pragma unroll
        for (int ni = 0; ni < 4; ni++) {
            const int n = n0 + warp_n * 32 + ni * 8 + tid4 * 2;
            const float2 bb = *reinterpret_cast<const float2*>(&bias[n]);
            #pragma unroll
            for (int hrow = 0; hrow < 2; hrow++) {
                const int m = m0 + warp_m * 64 + mi * 16 + gid + hrow * 8;
                float2 o;
                o.x = acc[mi][ni][hrow * 2 + 0] + bb.x;
                o.y = acc[mi][ni][hrow * 2 + 1] + bb.y;
                if (mode == 0) {
                    *reinterpret_cast<float2*>(&C[(size_t)m * DIM + n]) = o;
                } else {
                    const int b  = m >> 11;
                    const int t  = m & (T_ - 1);
                    const int h  = n >> 6;
                    const int hd = n & (HD - 1);
                    *reinterpret_cast<float2*>(
                        &C[((((size_t)b * NH + h) * T_) + t) * HD + hd]) = o;
                }
            }
        }
    }
}

// ===========================================================================
// Tensor-core flash attention (causal), split-bf16 3-term for S and PV.
// q,k,v: [B,H,T,HD] fp32; ctx out: [B,T,H,HD] fp32.
// CTA: 128 thr / 4 warps; q-tile 64 (16 rows/warp); kv-tile 64.
// ===========================================================================
#define AQT 64
#define AROWB 144                       // padded row: 72 halves
#define KV_TILE_B (64 * AROWB)          // 9216
#define OFF_KHI 0
#define OFF_KLO (KV_TILE_B)
#define OFF_VHI (2 * KV_TILE_B)
#define OFF_VLO (3 * KV_TILE_B)
#define OFF_PHI (4 * KV_TILE_B)
#define OFF_PLO (5 * KV_TILE_B)
#define ATTN_SMEM (6 * KV_TILE_B)       // 55296

__global__ void __launch_bounds__(128, 1) attn_tc_kernel(
    const float* __restrict__ q, const float* __restrict__ k,
    const float* __restrict__ v, float* __restrict__ ctx)
{
    extern __shared__ char smem[];
    const uint32_t sb = smem_to_u32(smem);
    const int tid  = threadIdx.x;
    const int lane = tid & 31;
    const int w    = tid >> 5;
    const int qt = gridDim.x - 1 - blockIdx.x;    // heavy tiles first
    const int h  = blockIdx.y;
    const int b  = blockIdx.z;
    const int q0 = qt * AQT;

    const size_t head = ((size_t)b * NH + h) * T_ * HD;
    const float* qp = q + head;
    const float* kp = k + head;
    const float* vp = v + head;

    const int r    = lane & 7;
    const int quad = lane >> 3;
    const int gid  = lane >> 2;
    const int tid4 = lane & 3;
    // a-pattern: rows (quad&1)*8+r, col (quad>>1)*16B  (A frags, P frags, V-trans)
    const uint32_t a_off =
        (uint32_t)((quad & 1) * 8 + r) * AROWB + (quad >> 1) * 16;
    // b-pattern: rows (quad>>1)*8+r, col (quad&1)*16B  (K frags)
    const uint32_t b_off =
        (uint32_t)((quad >> 1) * 8 + r) * AROWB + (quad & 1) * 16;

    // ---- stage Q (scaled by 1/8) into K buffers, ldmatrix A-frags ----
    #pragma unroll
    for (int l = 0; l < 8; l++) {
        const int f   = l * 128 + tid;
        const int row = f >> 4;
        const int c4  = f & 15;
        float4 vq = *reinterpret_cast<const float4*>(
            &qp[(size_t)(q0 + row) * HD + c4 * 4]);
        vq.x *= 0.125f; vq.y *= 0.125f; vq.z *= 0.125f; vq.w *= 0.125f;
        uint2 hi, lo;
        split4(vq, hi, lo);
        const uint32_t off = (uint32_t)row * AROWB + c4 * 8;
        *reinterpret_cast<uint2*>(smem + OFF_KHI + off) = hi;
        *reinterpret_cast<uint2*>(smem + OFF_KLO + off) = lo;
    }
    __syncthreads();

    uint32_t qh[4][4], ql[4][4];
    #pragma unroll
    for (int ks = 0; ks < 4; ks++) {
        const uint32_t addr = sb + (uint32_t)(w * 16) * AROWB + a_off + ks * 32;
        LDSM_X4(qh[ks], addr + OFF_KHI);
        LDSM_X4(ql[ks], addr + OFF_KLO);
    }

    float c_acc[8][4];
    #pragma unroll
    for (int nt = 0; nt < 8; nt++)
        #pragma unroll
        for (int j = 0; j < 4; j++) c_acc[nt][j] = 0.0f;
    float m0r = -INFINITY, m1r = -INFINITY;
    float l0r = 0.0f, l1r = 0.0f;

    for (int jt = 0; jt <= qt; ++jt) {
        __syncthreads();   // prev iter's K/V smem reads done (also covers Q stage)
        const int j0 = jt * AQT;

        // ---- load K,V tile (64x64 fp32 each), split, store ----
        #pragma unroll
        for (int l = 0; l < 8; l++) {
            const int f   = l * 128 + tid;
            const int row = f >> 4;
            const int c4  = f & 15;
            const uint32_t off = (uint32_t)row * AROWB + c4 * 8;
            uint2 hi, lo;
            float4 vk = *reinterpret_cast<const float4*>(
                &kp[(size_t)(j0 + row) * HD + c4 * 4]);
            split4(vk, hi, lo);
            *reinterpret_cast<uint2*>(smem + OFF_KHI + off) = hi;
            *reinterpret_cast<uint2*>(smem + OFF_KLO + off) = lo;
            float4 vv = *reinterpret_cast<const float4*>(
                &vp[(size_t)(j0 + row) * HD + c4 * 4]);
            split4(vv, hi, lo);
            *reinterpret_cast<uint2*>(smem + OFF_VHI + off) = hi;
            *reinterpret_cast<uint2*>(smem + OFF_VLO + off) = lo;
        }
        __syncthreads();

        // ---- S = Q @ K^T (3-term split) ----
        float s[8][4];
        #pragma unroll
        for (int nt = 0; nt < 8; nt++)
            #pragma unroll
            for (int j = 0; j < 4; j++) s[nt][j] = 0.0f;

        #pragma unroll
        for (int ks = 0; ks < 4; ++ks) {
            uint32_t kb[4][4];
            #pragma unroll
            for (int p2 = 0; p2 < 4; p2++) {
                LDSM_X4(kb[p2], sb + OFF_KHI + (uint32_t)(p2 * 16) * AROWB
                                + b_off + ks * 32);
            }
            #pragma unroll
            for (int p2 = 0; p2 < 4; p2++) {
                MMA_BF16(s[2 * p2 + 0], qh[ks], &kb[p2][0]);
                MMA_BF16(s[2 * p2 + 1], qh[ks], &kb[p2][2]);
                MMA_BF16(s[2 * p2 + 0], ql[ks], &kb[p2][0]);
                MMA_BF16(s[2 * p2 + 1], ql[ks], &kb[p2][2]);
            }
            #pragma unroll
            for (int p2 = 0; p2 < 4; p2++) {
                LDSM_X4(kb[p2], sb + OFF_KLO + (uint32_t)(p2 * 16) * AROWB
                                + b_off + ks * 32);
            }
            #pragma unroll
            for (int p2 = 0; p2 < 4; p2++) {
                MMA_BF16(s[2 * p2 + 0], qh[ks], &kb[p2][0]);
                MMA_BF16(s[2 * p2 + 1], qh[ks], &kb[p2][2]);
            }
        }

        // ---- causal mask on diagonal tile ----
        const int row0 = w * 16 + gid;      // local q row (0..63)
        const int row1 = row0 + 8;
        if (jt == qt) {
            #pragma unroll
            for (int nt = 0; nt < 8; nt++) {
                const int col0 = nt * 8 + tid4 * 2;
                if (col0     > row0) s[nt][0] = -INFINITY;
                if (col0 + 1 > row0) s[nt][1] = -INFINITY;
                if (col0     > row1) s[nt][2] = -INFINITY;
                if (col0 + 1 > row1) s[nt][3] = -INFINITY;
            }
        }

        // ---- online softmax ----
        float mt0 = -INFINITY, mt1 = -INFINITY;
        #pragma unroll
        for (int nt = 0; nt < 8; nt++) {
            mt0 = fmaxf(mt0, fmaxf(s[nt][0], s[nt][1]));
            mt1 = fmaxf(mt1, fmaxf(s[nt][2], s[nt][3]));
        }
        mt0 = fmaxf(mt0, __shfl_xor_sync(0xffffffffu, mt0, 1));
        mt0 = fmaxf(mt0, __shfl_xor_sync(0xffffffffu, mt0, 2));
        mt1 = fmaxf(mt1, __shfl_xor_sync(0xffffffffu, mt1, 1));
        mt1 = fmaxf(mt1, __shfl_xor_sync(0xffffffffu, mt1, 2));

        const float mn0 = fmaxf(m0r, mt0);
        const float mn1 = fmaxf(m1r, mt1);
        const float sc0 = __expf(m0r - mn0);
        const float sc1 = __expf(m1r - mn1);
        m0r = mn0; m1r = mn1;

        float ls0 = 0.0f, ls1 = 0.0f;
        #pragma unroll
        for (int nt = 0; nt < 8; nt++) {
            s[nt][0] = __expf(s[nt][0] - mn0);
            s[nt][1] = __expf(s[nt][1] - mn0);
            s[nt][2] = __expf(s[nt][2] - mn1);
            s[nt][3] = __expf(s[nt][3] - mn1);
            ls0 += s[nt][0] + s[nt][1];
            ls1 += s[nt][2] + s[nt][3];
        }
        ls0 += __shfl_xor_sync(0xffffffffu, ls0, 1);
        ls0 += __shfl_xor_sync(0xffffffffu, ls0, 2);
        ls1 += __shfl_xor_sync(0xffffffffu, ls1, 1);
        ls1 += __shfl_xor_sync(0xffffffffu, ls1, 2);
        l0r = l0r * sc0 + ls0;
        l1r = l1r * sc1 + ls1;

        #pragma unroll
        for (int nt = 0; nt < 8; nt++) {
            c_acc[nt][0] *= sc0; c_acc[nt][1] *= sc0;
            c_acc[nt][2] *= sc1; c_acc[nt][3] *= sc1;
        }

        // ---- write P (split bf16) to per-warp smem ----
        #pragma unroll
        for (int nt = 0; nt < 8; nt++) {
            __nv_bfloat162 h01 = __floats2bfloat162_rn(s[nt][0], s[nt][1]);
            __nv_bfloat162 l01 = __floats2bfloat162_rn(
                s[nt][0] - __bfloat162float(h01.x),
                s[nt][1] - __bfloat162float(h01.y));
            __nv_bfloat162 h23 = __floats2bfloat162_rn(s[nt][2], s[nt][3]);
            __nv_bfloat162 l23 = __floats2bfloat162_rn(
                s[nt][2] - __bfloat162float(h23.x),
                s[nt][3] - __bfloat162float(h23.y));
            const uint32_t c0 = (uint32_t)(nt * 16 + tid4 * 4);
            const uint32_t o0 = (uint32_t)row0 * AROWB + c0;
            const uint32_t o1 = (uint32_t)row1 * AROWB + c0;
            *reinterpret_cast<uint32_t*>(smem + OFF_PHI + o0) =
                *reinterpret_cast<uint32_t*>(&h01);
            *reinterpret_cast<uint32_t*>(smem + OFF_PLO + o0) =
                *reinterpret_cast<uint32_t*>(&l01);
            *reinterpret_cast<uint32_t*>(smem + OFF_PHI + o1) =
                *reinterpret_cast<uint32_t*>(&h23);
            *reinterpret_cast<uint32_t*>(smem + OFF_PLO + o1) =
                *reinterpret_cast<uint32_t*>(&l23);
        }
        __syncwarp();

        // ---- ctx += P @ V (3-term split) ----
        #pragma unroll
        for (int kk = 0; kk < 4; ++kk) {
            uint32_t ph[4], pl[4];
            const uint32_t paddr =
                sb + (uint32_t)(w * 16) * AROWB + a_off + kk * 32;
            LDSM_X4(ph, paddr + OFF_PHI);
            LDSM_X4(pl, paddr + OFF_PLO);

            uint32_t vb[4][4];
            #pragma unroll
            for (int nt2 = 0; nt2 < 4; nt2++) {
                LDSM_X4_T(vb[nt2], sb + OFF_VHI + (uint32_t)(kk * 16) * AROWB
                                   + a_off + nt2 * 32);
            }
            #pragma unroll
            for (int nt2 = 0; nt2 < 4; nt2++) {
                MMA_BF16(c_acc[2 * nt2 + 0], ph, &vb[nt2][0]);
                MMA_BF16(c_acc[2 * nt2 + 1], ph, &vb[nt2][2]);
                MMA_BF16(c_acc[2 * nt2 + 0], pl, &vb[nt2][0]);
                MMA_BF16(c_acc[2 * nt2 + 1], pl, &vb[nt2][2]);
            }
            #pragma unroll
            for (int nt2 = 0; nt2 < 4; nt2++) {
                LDSM_X4_T(vb[nt2], sb + OFF_VLO + (uint32_t)(kk * 16) * AROWB
                                   + a_off + nt2 * 32);
            }
            #pragma unroll
            for (int nt2 = 0; nt2 < 4; nt2++) {
                MMA_BF16(c_acc[2 * nt2 + 0], ph, &vb[nt2][0]);
                MMA_BF16(c_acc[2 * nt2 + 1], ph, &vb[nt2][2]);
            }
        }
    }

    // ---- epilogue: ctx / l -> [B,T,H,HD] ----
    const float inv0 = 1.0f / l0r;
    const float inv1 = 1.0f / l1r;
    const int qr0 = q0 + w * 16 + gid;
    const int qr1 = qr0 + 8;
    #pragma unroll
    for (int nt = 0; nt < 8; nt++) {
        const int hd = nt * 8 + tid4 * 2;
        float2 o0, o1;
        o0.x = c_acc[nt][0] * inv0; o0.y = c_acc[nt][1] * inv0;
        o1.x = c_acc[nt][2] * inv1; o1.y = c_acc[nt][3] * inv1;
        *reinterpret_cast<float2*>(
            &ctx[(((size_t)b * T_ + qr0) * NH + h) * HD + hd]) = o0;
        *reinterpret_cast<float2*>(
            &ctx[(((size_t)b * T_ + qr1) * NH + h) * HD + hd]) = o1;
    }
}

// ---------------------------------------------------------------------------
// kernel_launch
// ---------------------------------------------------------------------------
extern "C" void kernel_launch(void* const* d_in, const int* in_sizes, int n_in,
                              void* d_out, int out_size)
{
    const float* x  = (const float*)d_in[0];
    const float* Wq = (const float*)d_in[1];
    const float* bq = (const float*)d_in[2];
    const float* Wk = (const float*)d_in[3];
    const float* bk = (const float*)d_in[4];
    const float* Wv = (const float*)d_in[5];
    const float* bv = (const float*)d_in[6];
    const float* Wo = (const float*)d_in[7];
    const float* bo = (const float*)d_in[8];

    float* out   = (float*)d_out;
    float* k_out = out + (size_t)B_ * T_ * DIM;       // [B,H,T,Hd]
    float* v_out = out + (size_t)2 * B_ * T_ * DIM;   // [B,H,T,Hd]

    float* qbuf   = nullptr;
    float* ctxbuf = nullptr;
    cudaGetSymbolAddress((void**)&qbuf,   g_q);
    cudaGetSymbolAddress((void**)&ctxbuf, g_ctx);

    cudaFuncSetAttribute(gemm_tc_kernel,
                         cudaFuncAttributeMaxDynamicSharedMemorySize, GEMM_SMEM);
    cudaFuncSetAttribute(attn_tc_kernel,
                         cudaFuncAttributeMaxDynamicSharedMemorySize, ATTN_SMEM);

    dim3 ggrid(DIM / 128, M_TOT / 128);   // (8, 32)

    // QKV projections (mode 1: scatter to [B,H,T,Hd])
    gemm_tc_kernel<<<ggrid, 256, GEMM_SMEM>>>(x, Wq, bq, qbuf,  1);
    gemm_tc_kernel<<<ggrid, 256, GEMM_SMEM>>>(x, Wk, bk, k_out, 1);
    gemm_tc_kernel<<<ggrid, 256, GEMM_SMEM>>>(x, Wv, bv, v_out, 1);

    // Causal flash attention (tensor cores) -> ctx [B,T,H,Hd]
    dim3 agrid(T_ / AQT, NH, B_);         // (32, 16, 2)
    attn_tc_kernel<<<agrid, 128, ATTN_SMEM>>>(qbuf, k_out, v_out, ctxbuf);

    // Output projection (mode 0: row-major [B*T, DIM])
    gemm_tc_kernel<<<ggrid, 256, GEMM_SMEM>>>(ctxbuf, Wo, bo, out, 0);
}